// round 10
// baseline (speedup 1.0000x reference)
#include <cuda_runtime.h>

// Problem constants
#define BB   4
#define SS   4096
#define DIN  768
#define HD   64
#define MM   (BB*SS)   // 16384 rows
#define NSPLIT 4
#define NQT  64        // q-tiles per batch
#define NPART (NQT * NSPLIT)   // 256 partials per batch

// Scratch (device globals: allocation-free)
__device__ float g_q[MM * HD];
__device__ float g_k[MM * HD];
__device__ float g_v[MM * HD];
__device__ float g_po[BB * NPART * 64 * HD];   // unnormalized partial O
__device__ float g_pm[BB * NPART * 64];        // partial row max
__device__ float g_pl[BB * NPART * 64];        // partial row sum

// ---------------------------------------------------------------------------
// tf32 helpers
// ---------------------------------------------------------------------------
__device__ __forceinline__ unsigned f2tf(float f) {
    unsigned u;
    asm("cvt.rna.tf32.f32 %0, %1;" : "=r"(u) : "f"(f));
    return u;
}
__device__ __forceinline__ uint4 f2tf4(float4 v) {
    uint4 t;
    t.x = f2tf(v.x); t.y = f2tf(v.y); t.z = f2tf(v.z); t.w = f2tf(v.w);
    return t;
}
// D = A(m16 x k8, row) * B(k8 x n8, col) + D   (tf32 in, f32 accum)
__device__ __forceinline__ void mma8(float* c, const unsigned* a,
                                     unsigned b0, unsigned b1) {
    asm("mma.sync.aligned.m16n8k8.row.col.f32.tf32.tf32.f32 "
        "{%0,%1,%2,%3},{%4,%5,%6,%7},{%8,%9},{%0,%1,%2,%3};"
        : "+f"(c[0]), "+f"(c[1]), "+f"(c[2]), "+f"(c[3])
        : "r"(a[0]), "r"(a[1]), "r"(a[2]), "r"(a[3]), "r"(b0), "r"(b1));
}
__device__ __forceinline__ void cpa16(unsigned smem_dst, const void* gsrc) {
    asm volatile("cp.async.cg.shared.global [%0], [%1], 16;"
                 :: "r"(smem_dst), "l"(gsrc));
}
__device__ __forceinline__ void cpa_commit() {
    asm volatile("cp.async.commit_group;");
}
__device__ __forceinline__ void cpa_wait0() {
    asm volatile("cp.async.wait_group 0;");
}

// ---------------------------------------------------------------------------
// Kernel 1: fused QKV projection.  BM=32, N=192 fused.  grid = 512, block 256.
// 8 warps = 2(m) x 4(n); each warp m16 x n48 (6 n-frags). BK = 32.
// Double-buffered smem -> ONE barrier per k-iter.
// ---------------------------------------------------------------------------
__global__ __launch_bounds__(256) void qkv_kernel(
    const float* __restrict__ x,
    const float* __restrict__ Wq,
    const float* __restrict__ Wk,
    const float* __restrict__ Wv)
{
    __shared__ unsigned Xs[2][32][36];    // [m][k] tf32
    __shared__ unsigned Ws[2][32][200];   // [k][n=192] tf32

    const int tid  = threadIdx.x;
    const int lane = tid & 31;
    const int warp = tid >> 5;
    const int lq = lane >> 2;
    const int lr = lane & 3;
    const int wm = (warp >> 2) * 16;      // 0,16
    const int wn = (warp & 3) * 48;       // 0,48,96,144
    const int m0 = blockIdx.x * 32;

    float c[6][4];
    #pragma unroll
    for (int nf = 0; nf < 6; nf++)
        #pragma unroll
        for (int j = 0; j < 4; j++) c[nf][j] = 0.f;

    // staging slots
    const int xrow = tid >> 3, xc4 = (tid & 7) * 4;        // X: 256 f4, 1/thread
    float4 xreg;
    float4 wreg[6];

    xreg = *(const float4*)&x[(size_t)(m0 + xrow) * DIN + xc4];
    #pragma unroll
    for (int r = 0; r < 6; r++) {
        int idx = tid + r * 256;
        int wsel = idx >> 9;
        int j = idx & 511;
        int row = j >> 4, c4 = (j & 15) * 4;
        const float* W = (wsel == 0) ? Wq : (wsel == 1) ? Wk : Wv;
        wreg[r] = *(const float4*)&W[(size_t)row * HD + c4];
    }

    int p = 0;
    for (int k0 = 0; k0 < DIN; k0 += 32, p ^= 1) {
        // commit staged tiles (cvt to tf32) into buffer p
        *(uint4*)&Xs[p][xrow][xc4] = f2tf4(xreg);
        #pragma unroll
        for (int r = 0; r < 6; r++) {
            int idx = tid + r * 256;
            int wsel = idx >> 9;
            int j = idx & 511;
            int row = j >> 4, c4 = (j & 15) * 4;
            *(uint4*)&Ws[p][row][wsel * 64 + c4] = f2tf4(wreg[r]);
        }
        __syncthreads();

        // prefetch next chunk
        if (k0 + 32 < DIN) {
            xreg = *(const float4*)&x[(size_t)(m0 + xrow) * DIN + k0 + 32 + xc4];
            #pragma unroll
            for (int r = 0; r < 6; r++) {
                int idx = tid + r * 256;
                int wsel = idx >> 9;
                int j = idx & 511;
                int row = j >> 4, c4 = (j & 15) * 4;
                const float* W = (wsel == 0) ? Wq : (wsel == 1) ? Wk : Wv;
                wreg[r] = *(const float4*)&W[(size_t)(k0 + 32 + row) * HD + c4];
            }
        }

        // compute from buffer p (no trailing barrier: next store hits buf p^1,
        // whose readers all finished before this iteration's barrier)
        #pragma unroll
        for (int kf = 0; kf < 4; kf++) {
            unsigned a[4];
            a[0] = Xs[p][wm + lq][kf * 8 + lr];
            a[1] = Xs[p][wm + lq + 8][kf * 8 + lr];
            a[2] = Xs[p][wm + lq][kf * 8 + 4 + lr];
            a[3] = Xs[p][wm + lq + 8][kf * 8 + 4 + lr];
            #pragma unroll
            for (int nf = 0; nf < 6; nf++) {
                unsigned b0 = Ws[p][kf * 8 + lr][wn + nf * 8 + lq];
                unsigned b1 = Ws[p][kf * 8 + 4 + lr][wn + nf * 8 + lq];
                mma8(c[nf], a, b0, b1);
            }
        }
    }

    #pragma unroll
    for (int nf = 0; nf < 6; nf++) {
        int gcol = wn + nf * 8;
        int which = gcol >> 6;
        int nc = (gcol & 63) + 2 * lr;
        float* outp = (which == 0) ? g_q : (which == 1) ? g_k : g_v;
        *(float2*)&outp[(size_t)(m0 + wm + lq) * HD + nc] =
            make_float2(c[nf][0], c[nf][1]);
        *(float2*)&outp[(size_t)(m0 + wm + lq + 8) * HD + nc] =
            make_float2(c[nf][2], c[nf][3]);
    }
}

// ---------------------------------------------------------------------------
// Kernel 2: causal flash attention, tf32 mma + cp.async, SPLIT-K (4 splits).
// grid = (256, B): qs -> idx = qs>>2 (q-tile 63-idx, big first), split = qs&3.
// Each CTA: 4 warps, BM=64, keys [lo,hi) of its q-tile; writes unnormalized
// partial O + (m,l) stats.  3 CTAs/SM.
// ---------------------------------------------------------------------------
#define KS_W 68
#define VS_W 72
#define PS_W 68
#define KS_SZ (64 * KS_W)
#define VS_SZ (64 * VS_W)
#define SMEM_ATTN ((KS_SZ + 2 * VS_SZ + 64 * PS_W) * (int)sizeof(unsigned))

__global__ __launch_bounds__(128, 3) void attn_kernel()
{
    extern __shared__ unsigned smu[];
    unsigned* Ks = smu;                      // [64][68]
    unsigned* Vs = smu + KS_SZ;              // [2][64][72]
    unsigned* Ps = smu + KS_SZ + 2 * VS_SZ;  // [64][68]

    const int b     = blockIdx.y;
    const int qs    = blockIdx.x;            // 0..255
    const int idx   = qs >> 2;
    const int split = qs & 3;
    const int qi    = 63 - idx;              // big tiles first
    const int nb    = qi + 1;
    const int qtr   = (nb + 3) >> 2;
    const int lo    = split * qtr;
    const int hi    = (lo + qtr < nb) ? (lo + qtr) : nb;

    const int tid  = threadIdx.x;
    const int lane = tid & 31;
    const int warp = tid >> 5;
    const int lq = lane >> 2;
    const int lr = lane & 3;
    const int wm = warp * 16;

    const size_t pbase = ((size_t)b * NPART + qs) * 64;

    if (lo >= hi) {                          // empty split
        if (tid < 64) {
            g_pm[pbase + tid] = -1e30f;
            g_pl[pbase + tid] = 0.f;
        }
        return;
    }

    const float* __restrict__ qb = g_q + ((size_t)b * SS + qi * 64) * HD;
    const float* __restrict__ kg = g_k + (size_t)b * SS * HD;
    const float* __restrict__ vg = g_v + (size_t)b * SS * HD;

    unsigned kdst[8], vdst0[8], vdst1[8];
    size_t goff[8];
    #pragma unroll
    for (int r = 0; r < 8; r++) {
        int i2 = tid + r * 128;
        int row = i2 >> 4, c4 = (i2 & 15) * 4;
        kdst[r]  = (unsigned)__cvta_generic_to_shared(&Ks[row * KS_W + c4]);
        vdst0[r] = (unsigned)__cvta_generic_to_shared(&Vs[row * VS_W + c4]);
        vdst1[r] = (unsigned)__cvta_generic_to_shared(&Vs[VS_SZ + row * VS_W + c4]);
        goff[r]  = (size_t)row * HD + c4;
    }

    // ---- issue K[lo], V[lo] ----
    {
        const float* ks0 = kg + (size_t)lo * 64 * HD;
        const float* vs0 = vg + (size_t)lo * 64 * HD;
        #pragma unroll
        for (int r = 0; r < 8; r++) {
            cpa16(kdst[r],  ks0 + goff[r]);
            cpa16(vdst0[r], vs0 + goff[r]);
        }
        cpa_commit();
    }

    // ---- stage Q (scaled 1/8, tf32) through Ps, build A fragments ----
    #pragma unroll
    for (int r = 0; r < 8; r++) {
        int i2 = tid + r * 128;
        int row = i2 >> 4, c4 = (i2 & 15) * 4;
        float4 v = *(const float4*)&qb[(size_t)row * HD + c4];
        uint4 t;
        t.x = f2tf(v.x * 0.125f); t.y = f2tf(v.y * 0.125f);
        t.z = f2tf(v.z * 0.125f); t.w = f2tf(v.w * 0.125f);
        *(uint4*)&Ps[row * PS_W + c4] = t;
    }
    __syncthreads();

    unsigned aq[8][4];
    #pragma unroll
    for (int kf = 0; kf < 8; kf++) {
        aq[kf][0] = Ps[(wm + lq) * PS_W + kf * 8 + lr];
        aq[kf][1] = Ps[(wm + lq + 8) * PS_W + kf * 8 + lr];
        aq[kf][2] = Ps[(wm + lq) * PS_W + kf * 8 + 4 + lr];
        aq[kf][3] = Ps[(wm + lq + 8) * PS_W + kf * 8 + 4 + lr];
    }

    float m0 = -1e30f, m1 = -1e30f, l0 = 0.f, l1 = 0.f;
    float o[8][4];
    #pragma unroll
    for (int nf = 0; nf < 8; nf++)
        #pragma unroll
        for (int j = 0; j < 4; j++) o[nf][j] = 0.f;

    cpa_wait0();
    __syncthreads();

    for (int kb = lo; kb < hi; kb++) {
        const int par = (kb - lo) & 1;
        unsigned* Vb = Vs + par * VS_SZ;

        // issue V_{kb+1}
        if (kb + 1 < hi) {
            const float* vsrc = vg + (size_t)(kb + 1) * 64 * HD;
            unsigned* vd = par ? vdst0 : vdst1;
            #pragma unroll
            for (int r = 0; r < 8; r++) cpa16(vd[r], vsrc + goff[r]);
            cpa_commit();
        }

        // ---- S = Q K^T ----
        float s[8][4];
        #pragma unroll
        for (int nf = 0; nf < 8; nf++)
            #pragma unroll
            for (int j = 0; j < 4; j++) s[nf][j] = 0.f;

        #pragma unroll
        for (int kf = 0; kf < 8; kf++) {
            #pragma unroll
            for (int nf = 0; nf < 8; nf++) {
                unsigned b0 = Ks[(nf * 8 + lq) * KS_W + kf * 8 + lr];
                unsigned b1 = Ks[(nf * 8 + lq) * KS_W + kf * 8 + 4 + lr];
                mma8(s[nf], aq[kf], b0, b1);
            }
        }
        __syncthreads();

        // issue K_{kb+1}
        if (kb + 1 < hi) {
            const float* ksrc = kg + (size_t)(kb + 1) * 64 * HD;
            #pragma unroll
            for (int r = 0; r < 8; r++) cpa16(kdst[r], ksrc + goff[r]);
            cpa_commit();
        }

        // causal mask on diagonal block
        if (kb == qi) {
            int r0 = wm + lq, r1 = r0 + 8;
            #pragma unroll
            for (int nf = 0; nf < 8; nf++) {
                int cc = nf * 8 + 2 * lr;
                if (cc     > r0) s[nf][0] = -1e30f;
                if (cc + 1 > r0) s[nf][1] = -1e30f;
                if (cc     > r1) s[nf][2] = -1e30f;
                if (cc + 1 > r1) s[nf][3] = -1e30f;
            }
        }

        // ---- online softmax ----
        float mx0 = -1e30f, mx1 = -1e30f;
        #pragma unroll
        for (int nf = 0; nf < 8; nf++) {
            mx0 = fmaxf(mx0, fmaxf(s[nf][0], s[nf][1]));
            mx1 = fmaxf(mx1, fmaxf(s[nf][2], s[nf][3]));
        }
        mx0 = fmaxf(mx0, __shfl_xor_sync(0xffffffffu, mx0, 1));
        mx0 = fmaxf(mx0, __shfl_xor_sync(0xffffffffu, mx0, 2));
        mx1 = fmaxf(mx1, __shfl_xor_sync(0xffffffffu, mx1, 1));
        mx1 = fmaxf(mx1, __shfl_xor_sync(0xffffffffu, mx1, 2));

        float mn0 = fmaxf(m0, mx0), mn1 = fmaxf(m1, mx1);
        float corr0 = __expf(m0 - mn0), corr1 = __expf(m1 - mn1);

        float sum0 = 0.f, sum1 = 0.f;
        #pragma unroll
        for (int nf = 0; nf < 8; nf++) {
            s[nf][0] = __expf(s[nf][0] - mn0);
            s[nf][1] = __expf(s[nf][1] - mn0);
            s[nf][2] = __expf(s[nf][2] - mn1);
            s[nf][3] = __expf(s[nf][3] - mn1);
            sum0 += s[nf][0] + s[nf][1];
            sum1 += s[nf][2] + s[nf][3];
        }
        sum0 += __shfl_xor_sync(0xffffffffu, sum0, 1);
        sum0 += __shfl_xor_sync(0xffffffffu, sum0, 2);
        sum1 += __shfl_xor_sync(0xffffffffu, sum1, 1);
        sum1 += __shfl_xor_sync(0xffffffffu, sum1, 2);

        l0 = l0 * corr0 + sum0;  m0 = mn0;
        l1 = l1 * corr1 + sum1;  m1 = mn1;

        #pragma unroll
        for (int nf = 0; nf < 8; nf++) {
            o[nf][0] *= corr0; o[nf][1] *= corr0;
            o[nf][2] *= corr1; o[nf][3] *= corr1;
        }

        // ---- P -> smem (warp-private), rebuild as A fragments ----
        #pragma unroll
        for (int nf = 0; nf < 8; nf++) {
            uint2 w0 = make_uint2(f2tf(s[nf][0]), f2tf(s[nf][1]));
            uint2 w1 = make_uint2(f2tf(s[nf][2]), f2tf(s[nf][3]));
            *(uint2*)&Ps[(wm + lq) * PS_W + nf * 8 + 2 * lr] = w0;
            *(uint2*)&Ps[(wm + lq + 8) * PS_W + nf * 8 + 2 * lr] = w1;
        }
        __syncwarp();

        // ---- O += P V ----
        #pragma unroll
        for (int kf = 0; kf < 8; kf++) {
            unsigned ap[4];
            ap[0] = Ps[(wm + lq) * PS_W + kf * 8 + lr];
            ap[1] = Ps[(wm + lq + 8) * PS_W + kf * 8 + lr];
            ap[2] = Ps[(wm + lq) * PS_W + kf * 8 + 4 + lr];
            ap[3] = Ps[(wm + lq + 8) * PS_W + kf * 8 + 4 + lr];
            #pragma unroll
            for (int nf = 0; nf < 8; nf++) {
                unsigned b0 = Vb[(kf * 8 + lr) * VS_W + nf * 8 + lq];
                unsigned b1 = Vb[(kf * 8 + 4 + lr) * VS_W + nf * 8 + lq];
                mma8(o[nf], ap, b0, b1);
            }
        }

        cpa_wait0();
        __syncthreads();
    }

    // ---- write partials (unnormalized O, m, l) ----
    #pragma unroll
    for (int nf = 0; nf < 8; nf++) {
        int cc = nf * 8 + 2 * lr;
        *(float2*)&g_po[(pbase + wm + lq) * HD + cc] =
            make_float2(o[nf][0], o[nf][1]);
        *(float2*)&g_po[(pbase + wm + lq + 8) * HD + cc] =
            make_float2(o[nf][2], o[nf][3]);
    }
    if (lr == 0) {
        g_pm[pbase + wm + lq]     = m0;
        g_pl[pbase + wm + lq]     = l0;
        g_pm[pbase + wm + lq + 8] = m1;
        g_pl[pbase + wm + lq + 8] = l1;
    }
}

// ---------------------------------------------------------------------------
// Kernel 3: merge the 4 splits per q-tile.
// grid = (64, B), block 256: thread handles (row = tid>>2, 16 cols).
// ---------------------------------------------------------------------------
__global__ __launch_bounds__(256) void merge_kernel(float* __restrict__ out)
{
    const int b   = blockIdx.y;
    const int idx = blockIdx.x;          // matches attn ordering
    const int qi  = 63 - idx;
    const int tid = threadIdx.x;
    const int row = tid >> 2;
    const int c16 = (tid & 3) * 16;

    const size_t pb = ((size_t)b * NPART + NSPLIT * idx) * 64;

    float mm[NSPLIT], ll[NSPLIT];
    float M = -1e30f;
    #pragma unroll
    for (int s = 0; s < NSPLIT; s++) {
        mm[s] = g_pm[pb + s * 64 + row];
        ll[s] = g_pl[pb + s * 64 + row];
        M = fmaxf(M, mm[s]);
    }
    float w[NSPLIT];
    float denom = 0.f;
    #pragma unroll
    for (int s = 0; s < NSPLIT; s++) {
        w[s] = (ll[s] > 0.f) ? __expf(mm[s] - M) : 0.f;
        denom += ll[s] * w[s];
    }
    float inv = 1.0f / denom;

    float acc[16];
    #pragma unroll
    for (int j = 0; j < 16; j++) acc[j] = 0.f;

    #pragma unroll
    for (int s = 0; s < NSPLIT; s++) {
        if (w[s] > 0.f) {
            const float* po = g_po + (pb + s * 64 + row) * HD + c16;
            #pragma unroll
            for (int j = 0; j < 16; j += 4) {
                float4 a = *(const float4*)&po[j];
                acc[j + 0] += a.x * w[s];
                acc[j + 1] += a.y * w[s];
                acc[j + 2] += a.z * w[s];
                acc[j + 3] += a.w * w[s];
            }
        }
    }

    float* op = out + ((size_t)b * SS + qi * 64 + row) * HD + c16;
    #pragma unroll
    for (int j = 0; j < 16; j += 4) {
        *(float4*)&op[j] = make_float4(acc[j] * inv, acc[j + 1] * inv,
                                       acc[j + 2] * inv, acc[j + 3] * inv);
    }
}

// ---------------------------------------------------------------------------
// kernel_launch
// ---------------------------------------------------------------------------
extern "C" void kernel_launch(void* const* d_in, const int* in_sizes, int n_in,
                              void* d_out, int out_size)
{
    const float* x  = (const float*)d_in[0];
    const float* Wq = (const float*)d_in[1];
    const float* Wk = (const float*)d_in[2];
    const float* Wv = (const float*)d_in[3];
    float* out = (float*)d_out;

    static int smem_set = 0;
    if (!smem_set) {
        cudaFuncSetAttribute(attn_kernel,
                             cudaFuncAttributeMaxDynamicSharedMemorySize,
                             SMEM_ATTN);
        smem_set = 1;
    }

    qkv_kernel<<<MM / 32, 256>>>(x, Wq, Wk, Wv);

    dim3 g2(NQT * NSPLIT, BB);
    attn_kernel<<<g2, 128, SMEM_ATTN>>>();

    dim3 g3(NQT, BB);
    merge_kernel<<<g3, 256>>>(out);
}

// round 12
// speedup vs baseline: 1.1156x; 1.1156x over previous
#include <cuda_runtime.h>

// Problem constants
#define BB   4
#define SS   4096
#define DIN  768
#define HD   64
#define MM   (BB*SS)   // 16384 rows
#define NSPLIT 4
#define NQT  64        // q-tiles per batch
#define NPART (NQT * NSPLIT)   // 256 partials per batch

// Scratch (device globals: allocation-free)
__device__ float g_q[MM * HD];
__device__ float g_k[MM * HD];
__device__ float g_v[MM * HD];
__device__ float g_po[BB * NPART * 64 * HD];   // unnormalized partial O
__device__ float g_pm[BB * NPART * 64];        // partial row max
__device__ float g_pl[BB * NPART * 64];        // partial row sum

// ---------------------------------------------------------------------------
// tf32 helpers
// ---------------------------------------------------------------------------
__device__ __forceinline__ unsigned f2tf(float f) {
    unsigned u;
    asm("cvt.rna.tf32.f32 %0, %1;" : "=r"(u) : "f"(f));
    return u;
}
__device__ __forceinline__ uint4 f2tf4(float4 v) {
    uint4 t;
    t.x = f2tf(v.x); t.y = f2tf(v.y); t.z = f2tf(v.z); t.w = f2tf(v.w);
    return t;
}
// D = A(m16 x k8, row) * B(k8 x n8, col) + D   (tf32 in, f32 accum)
__device__ __forceinline__ void mma8(float* c, const unsigned* a,
                                     unsigned b0, unsigned b1) {
    asm("mma.sync.aligned.m16n8k8.row.col.f32.tf32.tf32.f32 "
        "{%0,%1,%2,%3},{%4,%5,%6,%7},{%8,%9},{%0,%1,%2,%3};"
        : "+f"(c[0]), "+f"(c[1]), "+f"(c[2]), "+f"(c[3])
        : "r"(a[0]), "r"(a[1]), "r"(a[2]), "r"(a[3]), "r"(b0), "r"(b1));
}
__device__ __forceinline__ void cpa16(unsigned smem_dst, const void* gsrc) {
    asm volatile("cp.async.cg.shared.global [%0], [%1], 16;"
                 :: "r"(smem_dst), "l"(gsrc));
}
__device__ __forceinline__ void cpa_commit() {
    asm volatile("cp.async.commit_group;");
}
__device__ __forceinline__ void cpa_wait0() {
    asm volatile("cp.async.wait_group 0;");
}

// ---------------------------------------------------------------------------
// Kernel 1: fused QKV projection.  BM=64, N=192 fused.  grid = 256, block 256.
// 8 warps = 4(m) x 2(n); each warp m16 x n96 (12 n-frags). BK = 32.
// Double-buffered smem -> ONE barrier per k-iter.
// ---------------------------------------------------------------------------
__global__ __launch_bounds__(256) void qkv_kernel(
    const float* __restrict__ x,
    const float* __restrict__ Wq,
    const float* __restrict__ Wk,
    const float* __restrict__ Wv)
{
    __shared__ unsigned Xs[2][64][36];     // [m][k] tf32
    __shared__ unsigned Ws[2][32][200];    // [k][n=192] tf32

    const int tid  = threadIdx.x;
    const int lane = tid & 31;
    const int warp = tid >> 5;
    const int lq = lane >> 2;
    const int lr = lane & 3;
    const int wm = (warp >> 1) * 16;    // 0,16,32,48
    const int wn = (warp & 1) * 96;     // 0,96
    const int m0 = blockIdx.x * 64;

    float c[12][4];
    #pragma unroll
    for (int nf = 0; nf < 12; nf++)
        #pragma unroll
        for (int j = 0; j < 4; j++) c[nf][j] = 0.f;

    float4 xreg[2], wreg[6];

    #pragma unroll
    for (int r = 0; r < 2; r++) {
        int idx = tid + r * 256;              // 0..511
        int row = idx >> 3, c4 = (idx & 7) * 4;
        xreg[r] = *(const float4*)&x[(size_t)(m0 + row) * DIN + c4];
    }
    #pragma unroll
    for (int r = 0; r < 6; r++) {
        int idx = tid + r * 256;
        int wsel = idx >> 9;
        int j = idx & 511;
        int row = j >> 4, c4 = (j & 15) * 4;
        const float* W = (wsel == 0) ? Wq : (wsel == 1) ? Wk : Wv;
        wreg[r] = *(const float4*)&W[(size_t)row * HD + c4];
    }

    int p = 0;
    for (int k0 = 0; k0 < DIN; k0 += 32, p ^= 1) {
        // commit staged tiles (cvt to tf32) into buffer p
        #pragma unroll
        for (int r = 0; r < 2; r++) {
            int idx = tid + r * 256;
            int row = idx >> 3, c4 = (idx & 7) * 4;
            *(uint4*)&Xs[p][row][c4] = f2tf4(xreg[r]);
        }
        #pragma unroll
        for (int r = 0; r < 6; r++) {
            int idx = tid + r * 256;
            int wsel = idx >> 9;
            int j = idx & 511;
            int row = j >> 4, c4 = (j & 15) * 4;
            *(uint4*)&Ws[p][row][wsel * 64 + c4] = f2tf4(wreg[r]);
        }
        __syncthreads();

        // prefetch next chunk
        if (k0 + 32 < DIN) {
            #pragma unroll
            for (int r = 0; r < 2; r++) {
                int idx = tid + r * 256;
                int row = idx >> 3, c4 = (idx & 7) * 4;
                xreg[r] = *(const float4*)&x[(size_t)(m0 + row) * DIN + k0 + 32 + c4];
            }
            #pragma unroll
            for (int r = 0; r < 6; r++) {
                int idx = tid + r * 256;
                int wsel = idx >> 9;
                int j = idx & 511;
                int row = j >> 4, c4 = (j & 15) * 4;
                const float* W = (wsel == 0) ? Wq : (wsel == 1) ? Wk : Wv;
                wreg[r] = *(const float4*)&W[(size_t)(k0 + 32 + row) * HD + c4];
            }
        }

        // compute from buffer p (no trailing barrier: next store hits buf p^1,
        // whose readers all finished before this iteration's barrier)
        #pragma unroll
        for (int kf = 0; kf < 4; kf++) {
            unsigned a[4];
            a[0] = Xs[p][wm + lq][kf * 8 + lr];
            a[1] = Xs[p][wm + lq + 8][kf * 8 + lr];
            a[2] = Xs[p][wm + lq][kf * 8 + 4 + lr];
            a[3] = Xs[p][wm + lq + 8][kf * 8 + 4 + lr];
            #pragma unroll
            for (int nf = 0; nf < 12; nf++) {
                unsigned b0 = Ws[p][kf * 8 + lr][wn + nf * 8 + lq];
                unsigned b1 = Ws[p][kf * 8 + 4 + lr][wn + nf * 8 + lq];
                mma8(c[nf], a, b0, b1);
            }
        }
    }

    #pragma unroll
    for (int nf = 0; nf < 12; nf++) {
        int gcol = wn + nf * 8;
        int which = gcol >> 6;
        int nc = (gcol & 63) + 2 * lr;
        float* outp = (which == 0) ? g_q : (which == 1) ? g_k : g_v;
        *(float2*)&outp[(size_t)(m0 + wm + lq) * HD + nc] =
            make_float2(c[nf][0], c[nf][1]);
        *(float2*)&outp[(size_t)(m0 + wm + lq + 8) * HD + nc] =
            make_float2(c[nf][2], c[nf][3]);
    }
}

// ---------------------------------------------------------------------------
// Kernel 2: causal flash attention, tf32 mma + cp.async, SPLIT-K (4 splits).
// grid = (256, B): qs -> idx = qs>>2 (q-tile 63-idx, big first), split = qs&3.
// Each CTA: 4 warps, BM=64, keys [lo,hi) of its q-tile; writes unnormalized
// partial O + (m,l) stats.  3 CTAs/SM.
// ---------------------------------------------------------------------------
#define KS_W 68
#define VS_W 72
#define PS_W 68
#define KS_SZ (64 * KS_W)
#define VS_SZ (64 * VS_W)
#define SMEM_ATTN ((KS_SZ + 2 * VS_SZ + 64 * PS_W) * (int)sizeof(unsigned))

__global__ __launch_bounds__(128, 3) void attn_kernel()
{
    extern __shared__ unsigned smu[];
    unsigned* Ks = smu;                      // [64][68]
    unsigned* Vs = smu + KS_SZ;              // [2][64][72]
    unsigned* Ps = smu + KS_SZ + 2 * VS_SZ;  // [64][68]

    const int b     = blockIdx.y;
    const int qs    = blockIdx.x;            // 0..255
    const int idx   = qs >> 2;
    const int split = qs & 3;
    const int qi    = 63 - idx;              // big tiles first
    const int nb    = qi + 1;
    const int qtr   = (nb + 3) >> 2;
    const int lo    = split * qtr;
    const int hi    = (lo + qtr < nb) ? (lo + qtr) : nb;

    const int tid  = threadIdx.x;
    const int lane = tid & 31;
    const int warp = tid >> 5;
    const int lq = lane >> 2;
    const int lr = lane & 3;
    const int wm = warp * 16;

    const size_t pbase = ((size_t)b * NPART + qs) * 64;

    if (lo >= hi) {                          // empty split
        if (tid < 64) {
            g_pm[pbase + tid] = -1e30f;
            g_pl[pbase + tid] = 0.f;
        }
        return;
    }

    const float* __restrict__ qb = g_q + ((size_t)b * SS + qi * 64) * HD;
    const float* __restrict__ kg = g_k + (size_t)b * SS * HD;
    const float* __restrict__ vg = g_v + (size_t)b * SS * HD;

    unsigned kdst[8], vdst0[8], vdst1[8];
    size_t goff[8];
    #pragma unroll
    for (int r = 0; r < 8; r++) {
        int i2 = tid + r * 128;
        int row = i2 >> 4, c4 = (i2 & 15) * 4;
        kdst[r]  = (unsigned)__cvta_generic_to_shared(&Ks[row * KS_W + c4]);
        vdst0[r] = (unsigned)__cvta_generic_to_shared(&Vs[row * VS_W + c4]);
        vdst1[r] = (unsigned)__cvta_generic_to_shared(&Vs[VS_SZ + row * VS_W + c4]);
        goff[r]  = (size_t)row * HD + c4;
    }

    // ---- issue K[lo], V[lo] ----
    {
        const float* ks0 = kg + (size_t)lo * 64 * HD;
        const float* vs0 = vg + (size_t)lo * 64 * HD;
        #pragma unroll
        for (int r = 0; r < 8; r++) {
            cpa16(kdst[r],  ks0 + goff[r]);
            cpa16(vdst0[r], vs0 + goff[r]);
        }
        cpa_commit();
    }

    // ---- stage Q (scaled 1/8, tf32) through Ps, build A fragments ----
    #pragma unroll
    for (int r = 0; r < 8; r++) {
        int i2 = tid + r * 128;
        int row = i2 >> 4, c4 = (i2 & 15) * 4;
        float4 v = *(const float4*)&qb[(size_t)row * HD + c4];
        uint4 t;
        t.x = f2tf(v.x * 0.125f); t.y = f2tf(v.y * 0.125f);
        t.z = f2tf(v.z * 0.125f); t.w = f2tf(v.w * 0.125f);
        *(uint4*)&Ps[row * PS_W + c4] = t;
    }
    __syncthreads();

    unsigned aq[8][4];
    #pragma unroll
    for (int kf = 0; kf < 8; kf++) {
        aq[kf][0] = Ps[(wm + lq) * PS_W + kf * 8 + lr];
        aq[kf][1] = Ps[(wm + lq + 8) * PS_W + kf * 8 + lr];
        aq[kf][2] = Ps[(wm + lq) * PS_W + kf * 8 + 4 + lr];
        aq[kf][3] = Ps[(wm + lq + 8) * PS_W + kf * 8 + 4 + lr];
    }

    float m0 = -1e30f, m1 = -1e30f, l0 = 0.f, l1 = 0.f;
    float o[8][4];
    #pragma unroll
    for (int nf = 0; nf < 8; nf++)
        #pragma unroll
        for (int j = 0; j < 4; j++) o[nf][j] = 0.f;

    cpa_wait0();
    __syncthreads();

    for (int kb = lo; kb < hi; kb++) {
        const int par = (kb - lo) & 1;
        unsigned* Vb = Vs + par * VS_SZ;

        // issue V_{kb+1}
        if (kb + 1 < hi) {
            const float* vsrc = vg + (size_t)(kb + 1) * 64 * HD;
            unsigned* vd = par ? vdst0 : vdst1;
            #pragma unroll
            for (int r = 0; r < 8; r++) cpa16(vd[r], vsrc + goff[r]);
            cpa_commit();
        }

        // ---- S = Q K^T ----
        float s[8][4];
        #pragma unroll
        for (int nf = 0; nf < 8; nf++)
            #pragma unroll
            for (int j = 0; j < 4; j++) s[nf][j] = 0.f;

        #pragma unroll
        for (int kf = 0; kf < 8; kf++) {
            #pragma unroll
            for (int nf = 0; nf < 8; nf++) {
                unsigned b0 = Ks[(nf * 8 + lq) * KS_W + kf * 8 + lr];
                unsigned b1 = Ks[(nf * 8 + lq) * KS_W + kf * 8 + 4 + lr];
                mma8(s[nf], aq[kf], b0, b1);
            }
        }
        __syncthreads();

        // issue K_{kb+1}
        if (kb + 1 < hi) {
            const float* ksrc = kg + (size_t)(kb + 1) * 64 * HD;
            #pragma unroll
            for (int r = 0; r < 8; r++) cpa16(kdst[r], ksrc + goff[r]);
            cpa_commit();
        }

        // causal mask on diagonal block
        if (kb == qi) {
            int r0 = wm + lq, r1 = r0 + 8;
            #pragma unroll
            for (int nf = 0; nf < 8; nf++) {
                int cc = nf * 8 + 2 * lr;
                if (cc     > r0) s[nf][0] = -1e30f;
                if (cc + 1 > r0) s[nf][1] = -1e30f;
                if (cc     > r1) s[nf][2] = -1e30f;
                if (cc + 1 > r1) s[nf][3] = -1e30f;
            }
        }

        // ---- online softmax ----
        float mx0 = -1e30f, mx1 = -1e30f;
        #pragma unroll
        for (int nf = 0; nf < 8; nf++) {
            mx0 = fmaxf(mx0, fmaxf(s[nf][0], s[nf][1]));
            mx1 = fmaxf(mx1, fmaxf(s[nf][2], s[nf][3]));
        }
        mx0 = fmaxf(mx0, __shfl_xor_sync(0xffffffffu, mx0, 1));
        mx0 = fmaxf(mx0, __shfl_xor_sync(0xffffffffu, mx0, 2));
        mx1 = fmaxf(mx1, __shfl_xor_sync(0xffffffffu, mx1, 1));
        mx1 = fmaxf(mx1, __shfl_xor_sync(0xffffffffu, mx1, 2));

        float mn0 = fmaxf(m0, mx0), mn1 = fmaxf(m1, mx1);
        float corr0 = __expf(m0 - mn0), corr1 = __expf(m1 - mn1);

        float sum0 = 0.f, sum1 = 0.f;
        #pragma unroll
        for (int nf = 0; nf < 8; nf++) {
            s[nf][0] = __expf(s[nf][0] - mn0);
            s[nf][1] = __expf(s[nf][1] - mn0);
            s[nf][2] = __expf(s[nf][2] - mn1);
            s[nf][3] = __expf(s[nf][3] - mn1);
            sum0 += s[nf][0] + s[nf][1];
            sum1 += s[nf][2] + s[nf][3];
        }
        sum0 += __shfl_xor_sync(0xffffffffu, sum0, 1);
        sum0 += __shfl_xor_sync(0xffffffffu, sum0, 2);
        sum1 += __shfl_xor_sync(0xffffffffu, sum1, 1);
        sum1 += __shfl_xor_sync(0xffffffffu, sum1, 2);

        l0 = l0 * corr0 + sum0;  m0 = mn0;
        l1 = l1 * corr1 + sum1;  m1 = mn1;

        #pragma unroll
        for (int nf = 0; nf < 8; nf++) {
            o[nf][0] *= corr0; o[nf][1] *= corr0;
            o[nf][2] *= corr1; o[nf][3] *= corr1;
        }

        // ---- P -> smem (warp-private), rebuild as A fragments ----
        #pragma unroll
        for (int nf = 0; nf < 8; nf++) {
            uint2 w0 = make_uint2(f2tf(s[nf][0]), f2tf(s[nf][1]));
            uint2 w1 = make_uint2(f2tf(s[nf][2]), f2tf(s[nf][3]));
            *(uint2*)&Ps[(wm + lq) * PS_W + nf * 8 + 2 * lr] = w0;
            *(uint2*)&Ps[(wm + lq + 8) * PS_W + nf * 8 + 2 * lr] = w1;
        }
        __syncwarp();

        // ---- O += P V ----
        #pragma unroll
        for (int kf = 0; kf < 8; kf++) {
            unsigned ap[4];
            ap[0] = Ps[(wm + lq) * PS_W + kf * 8 + lr];
            ap[1] = Ps[(wm + lq + 8) * PS_W + kf * 8 + lr];
            ap[2] = Ps[(wm + lq) * PS_W + kf * 8 + 4 + lr];
            ap[3] = Ps[(wm + lq + 8) * PS_W + kf * 8 + 4 + lr];
            #pragma unroll
            for (int nf = 0; nf < 8; nf++) {
                unsigned b0 = Vb[(kf * 8 + lr) * VS_W + nf * 8 + lq];
                unsigned b1 = Vb[(kf * 8 + 4 + lr) * VS_W + nf * 8 + lq];
                mma8(o[nf], ap, b0, b1);
            }
        }

        cpa_wait0();
        __syncthreads();
    }

    // ---- write partials (unnormalized O, m, l) ----
    #pragma unroll
    for (int nf = 0; nf < 8; nf++) {
        int cc = nf * 8 + 2 * lr;
        *(float2*)&g_po[(pbase + wm + lq) * HD + cc] =
            make_float2(o[nf][0], o[nf][1]);
        *(float2*)&g_po[(pbase + wm + lq + 8) * HD + cc] =
            make_float2(o[nf][2], o[nf][3]);
    }
    if (lr == 0) {
        g_pm[pbase + wm + lq]     = m0;
        g_pl[pbase + wm + lq]     = l0;
        g_pm[pbase + wm + lq + 8] = m1;
        g_pl[pbase + wm + lq + 8] = l1;
    }
}

// ---------------------------------------------------------------------------
// Kernel 3: merge the 4 splits per q-tile.
// grid = (64, B), block 256: thread handles (row = tid>>2, 16 cols).
// ---------------------------------------------------------------------------
__global__ __launch_bounds__(256) void merge_kernel(float* __restrict__ out)
{
    const int b   = blockIdx.y;
    const int idx = blockIdx.x;          // matches attn ordering
    const int qi  = 63 - idx;
    const int tid = threadIdx.x;
    const int row = tid >> 2;
    const int c16 = (tid & 3) * 16;

    const size_t pb = ((size_t)b * NPART + NSPLIT * idx) * 64;

    float mm[NSPLIT], ll[NSPLIT];
    float M = -1e30f;
    #pragma unroll
    for (int s = 0; s < NSPLIT; s++) {
        mm[s] = g_pm[pb + s * 64 + row];
        ll[s] = g_pl[pb + s * 64 + row];
        M = fmaxf(M, mm[s]);
    }
    float w[NSPLIT];
    float denom = 0.f;
    #pragma unroll
    for (int s = 0; s < NSPLIT; s++) {
        w[s] = (ll[s] > 0.f) ? __expf(mm[s] - M) : 0.f;
        denom += ll[s] * w[s];
    }
    float inv = 1.0f / denom;

    float acc[16];
    #pragma unroll
    for (int j = 0; j < 16; j++) acc[j] = 0.f;

    #pragma unroll
    for (int s = 0; s < NSPLIT; s++) {
        if (w[s] > 0.f) {
            const float* po = g_po + (pb + s * 64 + row) * HD + c16;
            #pragma unroll
            for (int j = 0; j < 16; j += 4) {
                float4 a = *(const float4*)&po[j];
                acc[j + 0] += a.x * w[s];
                acc[j + 1] += a.y * w[s];
                acc[j + 2] += a.z * w[s];
                acc[j + 3] += a.w * w[s];
            }
        }
    }

    float* op = out + ((size_t)b * SS + qi * 64 + row) * HD + c16;
    #pragma unroll
    for (int j = 0; j < 16; j += 4) {
        *(float4*)&op[j] = make_float4(acc[j] * inv, acc[j + 1] * inv,
                                       acc[j + 2] * inv, acc[j + 3] * inv);
    }
}

// ---------------------------------------------------------------------------
// kernel_launch
// ---------------------------------------------------------------------------
extern "C" void kernel_launch(void* const* d_in, const int* in_sizes, int n_in,
                              void* d_out, int out_size)
{
    const float* x  = (const float*)d_in[0];
    const float* Wq = (const float*)d_in[1];
    const float* Wk = (const float*)d_in[2];
    const float* Wv = (const float*)d_in[3];
    float* out = (float*)d_out;

    static int smem_set = 0;
    if (!smem_set) {
        cudaFuncSetAttribute(attn_kernel,
                             cudaFuncAttributeMaxDynamicSharedMemorySize,
                             SMEM_ATTN);
        smem_set = 1;
    }

    qkv_kernel<<<MM / 64, 256>>>(x, Wq, Wk, Wv);

    dim3 g2(NQT * NSPLIT, BB);
    attn_kernel<<<g2, 128, SMEM_ATTN>>>();

    dim3 g3(NQT, BB);
    merge_kernel<<<g3, 256>>>(out);
}

// round 13
// speedup vs baseline: 1.1700x; 1.0488x over previous
#include <cuda_runtime.h>

// Problem constants
#define BB   4
#define SS   4096
#define DIN  768
#define HD   64
#define MM   (BB*SS)   // 16384 rows
#define NSPLIT 4
#define NQT  64        // q-tiles per batch
#define NPART (NQT * NSPLIT)   // 256 partials per batch

// Scratch (device globals: allocation-free)
__device__ float g_q[MM * HD];
__device__ float g_k[MM * HD];
__device__ float g_v[MM * HD];
__device__ float g_po[BB * NPART * 64 * HD];   // unnormalized partial O
__device__ float g_pm[BB * NPART * 64];        // partial row max
__device__ float g_pl[BB * NPART * 64];        // partial row sum
// Packed W: [kfg=96][lr=4][n=192] of float2{tf32(W[k][n]), tf32(W[k+4][n])},
// k = kfg*8+lr; n selects Wq/Wk/Wv by n>>6.
__device__ __align__(16) uint2 g_wp[96 * 4 * 192];

// ---------------------------------------------------------------------------
// tf32 helpers
// ---------------------------------------------------------------------------
__device__ __forceinline__ unsigned f2tf(float f) {
    unsigned u;
    asm("cvt.rna.tf32.f32 %0, %1;" : "=r"(u) : "f"(f));
    return u;
}
// D = A(m16 x k8, row) * B(k8 x n8, col) + D   (tf32 in, f32 accum)
__device__ __forceinline__ void mma8(float* c, const unsigned* a,
                                     unsigned b0, unsigned b1) {
    asm("mma.sync.aligned.m16n8k8.row.col.f32.tf32.tf32.f32 "
        "{%0,%1,%2,%3},{%4,%5,%6,%7},{%8,%9},{%0,%1,%2,%3};"
        : "+f"(c[0]), "+f"(c[1]), "+f"(c[2]), "+f"(c[3])
        : "r"(a[0]), "r"(a[1]), "r"(a[2]), "r"(a[3]), "r"(b0), "r"(b1));
}
__device__ __forceinline__ void cpa16(unsigned smem_dst, const void* gsrc) {
    asm volatile("cp.async.cg.shared.global [%0], [%1], 16;"
                 :: "r"(smem_dst), "l"(gsrc));
}
__device__ __forceinline__ void cpa_commit() {
    asm volatile("cp.async.commit_group;");
}
__device__ __forceinline__ void cpa_wait0() {
    asm volatile("cp.async.wait_group 0;");
}

// ---------------------------------------------------------------------------
// Kernel 0: pack W into g_wp (tf32 rna, paired k/k+4).  73728 uint2 total.
// grid = 288, block = 256.
// ---------------------------------------------------------------------------
__global__ __launch_bounds__(256) void wpack_kernel(
    const float* __restrict__ Wq,
    const float* __restrict__ Wk,
    const float* __restrict__ Wv)
{
    int idx = blockIdx.x * 256 + threadIdx.x;
    if (idx >= 96 * 4 * 192) return;
    int n  = idx % 192;
    int t  = idx / 192;          // = kfg*4 + lr
    int lr = t & 3;
    int kfg = t >> 2;
    int k = kfg * 8 + lr;
    int which = n >> 6, nc = n & 63;
    const float* W = (which == 0) ? Wq : (which == 1) ? Wk : Wv;
    g_wp[idx] = make_uint2(f2tf(W[(size_t)k * HD + nc]),
                           f2tf(W[(size_t)(k + 4) * HD + nc]));
}

// ---------------------------------------------------------------------------
// Kernel 1: fused QKV projection.  BM=64, N=192 fused.  grid = 256, block 256.
// 8 warps = 4(m) x 2(n); each warp m16 x n96 (12 n-frags). BK = 32.
// W via cp.async from pre-packed g_wp (LDS.64 B frags, conflict-free pad 196).
// X staged via registers with cvt.rna into paired layout (LDS.64 A frags).
// ---------------------------------------------------------------------------
__global__ __launch_bounds__(256) void qkv_kernel(const float* __restrict__ x)
{
    // Xs2[p][row][40 words]: slot (kf*4+j) holds {x[row][kf*8+j], x[row][kf*8+4+j]}
    // word index = (kf*4+j)*2 + pair.  Row stride 40 words -> lq stride 8 banks.
    __shared__ __align__(16) unsigned Xs2[2][64][40];
    // Ws2[p][kf*4+lr][392 words]: uint2 n-index 0..191, pad to 196 (row 1568B).
    __shared__ __align__(16) unsigned Ws2[2][16][392];

    const int tid  = threadIdx.x;
    const int lane = tid & 31;
    const int warp = tid >> 5;
    const int lq = lane >> 2;
    const int lr = lane & 3;
    const int wm = (warp >> 1) * 16;    // 0,16,32,48
    const int wn = (warp & 1) * 96;     // 0,96
    const int m0 = blockIdx.x * 64;

    float c[12][4];
    #pragma unroll
    for (int nf = 0; nf < 12; nf++)
        #pragma unroll
        for (int j = 0; j < 4; j++) c[nf][j] = 0.f;

    // W cp.async slots: 1536 16B-chunks per iter, 6 per thread.
    unsigned wdst[2][6];
    size_t   wsrc_off[6];
    #pragma unroll
    for (int r = 0; r < 6; r++) {
        int ch = tid + r * 256;             // 0..1535
        int wrow = ch / 96;                 // 0..15  (= kf_local*4 + lr)
        int wcol = ch - wrow * 96;          // 0..95
        wdst[0][r] = (unsigned)__cvta_generic_to_shared(
            (char*)&Ws2[0][0][0] + wrow * 1568 + wcol * 16);
        wdst[1][r] = (unsigned)__cvta_generic_to_shared(
            (char*)&Ws2[1][0][0] + wrow * 1568 + wcol * 16);
        wsrc_off[r] = (size_t)ch * 16;
    }

    // X staging slots: idx = tid + r*256 -> row = idx>>3, c4 = (idx&7)*4
    const int xrow0 = tid >> 3, xc40 = (tid & 7) * 4;
    const int xrow1 = (tid + 256) >> 3, xc41 = ((tid + 256) & 7) * 4;

    float4 xreg[2];
    xreg[0] = *(const float4*)&x[(size_t)(m0 + xrow0) * DIN + xc40];
    xreg[1] = *(const float4*)&x[(size_t)(m0 + xrow1) * DIN + xc41];

    // issue W chunk 0
    {
        const char* src = (const char*)g_wp;
        #pragma unroll
        for (int r = 0; r < 6; r++) cpa16(wdst[0][r], src + wsrc_off[r]);
        cpa_commit();
    }

    int p = 0;
    for (int k0 = 0; k0 < DIN; k0 += 32, p ^= 1) {
        // ---- commit staged X (cvt.rna) into paired layout, buffer p ----
        {
            int kf = xc40 >> 3, pair = (xc40 >> 2) & 1;
            unsigned* d = &Xs2[p][xrow0][kf * 8 + pair];
            d[0] = f2tf(xreg[0].x); d[2] = f2tf(xreg[0].y);
            d[4] = f2tf(xreg[0].z); d[6] = f2tf(xreg[0].w);
        }
        {
            int kf = xc41 >> 3, pair = (xc41 >> 2) & 1;
            unsigned* d = &Xs2[p][xrow1][kf * 8 + pair];
            d[0] = f2tf(xreg[1].x); d[2] = f2tf(xreg[1].y);
            d[4] = f2tf(xreg[1].z); d[6] = f2tf(xreg[1].w);
        }

        cpa_wait0();          // W_p landed (this thread's groups)
        __syncthreads();      // all threads: X_p + W_p visible

        // ---- prefetch next chunk (X regs + W cp.async into p^1) ----
        if (k0 + 32 < DIN) {
            xreg[0] = *(const float4*)&x[(size_t)(m0 + xrow0) * DIN + k0 + 32 + xc40];
            xreg[1] = *(const float4*)&x[(size_t)(m0 + xrow1) * DIN + k0 + 32 + xc41];
            const char* src = (const char*)g_wp + (size_t)((k0 >> 3) + 4) * 6144;
            #pragma unroll
            for (int r = 0; r < 6; r++) cpa16(wdst[p ^ 1][r], src + wsrc_off[r]);
            cpa_commit();
        }

        // ---- compute from buffer p ----
        #pragma unroll
        for (int kf = 0; kf < 4; kf++) {
            uint2 xlo = *(const uint2*)&Xs2[p][wm + lq][(kf * 4 + lr) * 2];
            uint2 xhi = *(const uint2*)&Xs2[p][wm + lq + 8][(kf * 4 + lr) * 2];
            unsigned a[4] = {xlo.x, xhi.x, xlo.y, xhi.y};
            #pragma unroll
            for (int nf = 0; nf < 12; nf++) {
                uint2 b = *(const uint2*)&Ws2[p][kf * 4 + lr][(wn + nf * 8 + lq) * 2];
                mma8(c[nf], a, b.x, b.y);
            }
        }
        // no trailing barrier: next iter writes buffers p^1, whose readers
        // finished before this iteration's barrier.
    }

    #pragma unroll
    for (int nf = 0; nf < 12; nf++) {
        int gcol = wn + nf * 8;
        int which = gcol >> 6;
        int nc = (gcol & 63) + 2 * lr;
        float* outp = (which == 0) ? g_q : (which == 1) ? g_k : g_v;
        *(float2*)&outp[(size_t)(m0 + wm + lq) * HD + nc] =
            make_float2(c[nf][0], c[nf][1]);
        *(float2*)&outp[(size_t)(m0 + wm + lq + 8) * HD + nc] =
            make_float2(c[nf][2], c[nf][3]);
    }
}

// ---------------------------------------------------------------------------
// Kernel 2: causal flash attention, tf32 mma + cp.async, SPLIT-K (4 splits).
// grid = (256, B): qs -> idx = qs>>2 (q-tile 63-idx, big first), split = qs&3.
// ---------------------------------------------------------------------------
#define KS_W 68
#define VS_W 72
#define PS_W 68
#define KS_SZ (64 * KS_W)
#define VS_SZ (64 * VS_W)
#define SMEM_ATTN ((KS_SZ + 2 * VS_SZ + 64 * PS_W) * (int)sizeof(unsigned))

__global__ __launch_bounds__(128, 3) void attn_kernel()
{
    extern __shared__ unsigned smu[];
    unsigned* Ks = smu;                      // [64][68]
    unsigned* Vs = smu + KS_SZ;              // [2][64][72]
    unsigned* Ps = smu + KS_SZ + 2 * VS_SZ;  // [64][68]

    const int b     = blockIdx.y;
    const int qs    = blockIdx.x;            // 0..255
    const int idx   = qs >> 2;
    const int split = qs & 3;
    const int qi    = 63 - idx;              // big tiles first
    const int nb    = qi + 1;
    const int qtr   = (nb + 3) >> 2;
    const int lo    = split * qtr;
    const int hi    = (lo + qtr < nb) ? (lo + qtr) : nb;

    const int tid  = threadIdx.x;
    const int lane = tid & 31;
    const int warp = tid >> 5;
    const int lq = lane >> 2;
    const int lr = lane & 3;
    const int wm = warp * 16;

    const size_t pbase = ((size_t)b * NPART + qs) * 64;

    if (lo >= hi) {                          // empty split
        if (tid < 64) {
            g_pm[pbase + tid] = -1e30f;
            g_pl[pbase + tid] = 0.f;
        }
        return;
    }

    const float* __restrict__ qb = g_q + ((size_t)b * SS + qi * 64) * HD;
    const float* __restrict__ kg = g_k + (size_t)b * SS * HD;
    const float* __restrict__ vg = g_v + (size_t)b * SS * HD;

    unsigned kdst[8], vdst0[8], vdst1[8];
    size_t goff[8];
    #pragma unroll
    for (int r = 0; r < 8; r++) {
        int i2 = tid + r * 128;
        int row = i2 >> 4, c4 = (i2 & 15) * 4;
        kdst[r]  = (unsigned)__cvta_generic_to_shared(&Ks[row * KS_W + c4]);
        vdst0[r] = (unsigned)__cvta_generic_to_shared(&Vs[row * VS_W + c4]);
        vdst1[r] = (unsigned)__cvta_generic_to_shared(&Vs[VS_SZ + row * VS_W + c4]);
        goff[r]  = (size_t)row * HD + c4;
    }

    // ---- issue K[lo], V[lo] ----
    {
        const float* ks0 = kg + (size_t)lo * 64 * HD;
        const float* vs0 = vg + (size_t)lo * 64 * HD;
        #pragma unroll
        for (int r = 0; r < 8; r++) {
            cpa16(kdst[r],  ks0 + goff[r]);
            cpa16(vdst0[r], vs0 + goff[r]);
        }
        cpa_commit();
    }

    // ---- stage Q (scaled 1/8, tf32) through Ps, build A fragments ----
    #pragma unroll
    for (int r = 0; r < 8; r++) {
        int i2 = tid + r * 128;
        int row = i2 >> 4, c4 = (i2 & 15) * 4;
        float4 v = *(const float4*)&qb[(size_t)row * HD + c4];
        uint4 t;
        t.x = f2tf(v.x * 0.125f); t.y = f2tf(v.y * 0.125f);
        t.z = f2tf(v.z * 0.125f); t.w = f2tf(v.w * 0.125f);
        *(uint4*)&Ps[row * PS_W + c4] = t;
    }
    __syncthreads();

    unsigned aq[8][4];
    #pragma unroll
    for (int kf = 0; kf < 8; kf++) {
        aq[kf][0] = Ps[(wm + lq) * PS_W + kf * 8 + lr];
        aq[kf][1] = Ps[(wm + lq + 8) * PS_W + kf * 8 + lr];
        aq[kf][2] = Ps[(wm + lq) * PS_W + kf * 8 + 4 + lr];
        aq[kf][3] = Ps[(wm + lq + 8) * PS_W + kf * 8 + 4 + lr];
    }

    float m0 = -1e30f, m1 = -1e30f, l0 = 0.f, l1 = 0.f;
    float o[8][4];
    #pragma unroll
    for (int nf = 0; nf < 8; nf++)
        #pragma unroll
        for (int j = 0; j < 4; j++) o[nf][j] = 0.f;

    cpa_wait0();
    __syncthreads();

    for (int kb = lo; kb < hi; kb++) {
        const int par = (kb - lo) & 1;
        unsigned* Vb = Vs + par * VS_SZ;

        // issue V_{kb+1}
        if (kb + 1 < hi) {
            const float* vsrc = vg + (size_t)(kb + 1) * 64 * HD;
            unsigned* vd = par ? vdst0 : vdst1;
            #pragma unroll
            for (int r = 0; r < 8; r++) cpa16(vd[r], vsrc + goff[r]);
            cpa_commit();
        }

        // ---- S = Q K^T ----
        float s[8][4];
        #pragma unroll
        for (int nf = 0; nf < 8; nf++)
            #pragma unroll
            for (int j = 0; j < 4; j++) s[nf][j] = 0.f;

        #pragma unroll
        for (int kf = 0; kf < 8; kf++) {
            #pragma unroll
            for (int nf = 0; nf < 8; nf++) {
                unsigned b0 = Ks[(nf * 8 + lq) * KS_W + kf * 8 + lr];
                unsigned b1 = Ks[(nf * 8 + lq) * KS_W + kf * 8 + 4 + lr];
                mma8(s[nf], aq[kf], b0, b1);
            }
        }
        __syncthreads();

        // issue K_{kb+1}
        if (kb + 1 < hi) {
            const float* ksrc = kg + (size_t)(kb + 1) * 64 * HD;
            #pragma unroll
            for (int r = 0; r < 8; r++) cpa16(kdst[r], ksrc + goff[r]);
            cpa_commit();
        }

        // causal mask on diagonal block
        if (kb == qi) {
            int r0 = wm + lq, r1 = r0 + 8;
            #pragma unroll
            for (int nf = 0; nf < 8; nf++) {
                int cc = nf * 8 + 2 * lr;
                if (cc     > r0) s[nf][0] = -1e30f;
                if (cc + 1 > r0) s[nf][1] = -1e30f;
                if (cc     > r1) s[nf][2] = -1e30f;
                if (cc + 1 > r1) s[nf][3] = -1e30f;
            }
        }

        // ---- online softmax ----
        float mx0 = -1e30f, mx1 = -1e30f;
        #pragma unroll
        for (int nf = 0; nf < 8; nf++) {
            mx0 = fmaxf(mx0, fmaxf(s[nf][0], s[nf][1]));
            mx1 = fmaxf(mx1, fmaxf(s[nf][2], s[nf][3]));
        }
        mx0 = fmaxf(mx0, __shfl_xor_sync(0xffffffffu, mx0, 1));
        mx0 = fmaxf(mx0, __shfl_xor_sync(0xffffffffu, mx0, 2));
        mx1 = fmaxf(mx1, __shfl_xor_sync(0xffffffffu, mx1, 1));
        mx1 = fmaxf(mx1, __shfl_xor_sync(0xffffffffu, mx1, 2));

        float mn0 = fmaxf(m0, mx0), mn1 = fmaxf(m1, mx1);
        float corr0 = __expf(m0 - mn0), corr1 = __expf(m1 - mn1);

        float sum0 = 0.f, sum1 = 0.f;
        #pragma unroll
        for (int nf = 0; nf < 8; nf++) {
            s[nf][0] = __expf(s[nf][0] - mn0);
            s[nf][1] = __expf(s[nf][1] - mn0);
            s[nf][2] = __expf(s[nf][2] - mn1);
            s[nf][3] = __expf(s[nf][3] - mn1);
            sum0 += s[nf][0] + s[nf][1];
            sum1 += s[nf][2] + s[nf][3];
        }
        sum0 += __shfl_xor_sync(0xffffffffu, sum0, 1);
        sum0 += __shfl_xor_sync(0xffffffffu, sum0, 2);
        sum1 += __shfl_xor_sync(0xffffffffu, sum1, 1);
        sum1 += __shfl_xor_sync(0xffffffffu, sum1, 2);

        l0 = l0 * corr0 + sum0;  m0 = mn0;
        l1 = l1 * corr1 + sum1;  m1 = mn1;

        #pragma unroll
        for (int nf = 0; nf < 8; nf++) {
            o[nf][0] *= corr0; o[nf][1] *= corr0;
            o[nf][2] *= corr1; o[nf][3] *= corr1;
        }

        // ---- P -> smem (warp-private), rebuild as A fragments ----
        #pragma unroll
        for (int nf = 0; nf < 8; nf++) {
            uint2 w0 = make_uint2(f2tf(s[nf][0]), f2tf(s[nf][1]));
            uint2 w1 = make_uint2(f2tf(s[nf][2]), f2tf(s[nf][3]));
            *(uint2*)&Ps[(wm + lq) * PS_W + nf * 8 + 2 * lr] = w0;
            *(uint2*)&Ps[(wm + lq + 8) * PS_W + nf * 8 + 2 * lr] = w1;
        }
        __syncwarp();

        // ---- O += P V ----
        #pragma unroll
        for (int kf = 0; kf < 8; kf++) {
            unsigned ap[4];
            ap[0] = Ps[(wm + lq) * PS_W + kf * 8 + lr];
            ap[1] = Ps[(wm + lq + 8) * PS_W + kf * 8 + lr];
            ap[2] = Ps[(wm + lq) * PS_W + kf * 8 + 4 + lr];
            ap[3] = Ps[(wm + lq + 8) * PS_W + kf * 8 + 4 + lr];
            #pragma unroll
            for (int nf = 0; nf < 8; nf++) {
                unsigned b0 = Vb[(kf * 8 + lr) * VS_W + nf * 8 + lq];
                unsigned b1 = Vb[(kf * 8 + 4 + lr) * VS_W + nf * 8 + lq];
                mma8(o[nf], ap, b0, b1);
            }
        }

        cpa_wait0();
        __syncthreads();
    }

    // ---- write partials (unnormalized O, m, l) ----
    #pragma unroll
    for (int nf = 0; nf < 8; nf++) {
        int cc = nf * 8 + 2 * lr;
        *(float2*)&g_po[(pbase + wm + lq) * HD + cc] =
            make_float2(o[nf][0], o[nf][1]);
        *(float2*)&g_po[(pbase + wm + lq + 8) * HD + cc] =
            make_float2(o[nf][2], o[nf][3]);
    }
    if (lr == 0) {
        g_pm[pbase + wm + lq]     = m0;
        g_pl[pbase + wm + lq]     = l0;
        g_pm[pbase + wm + lq + 8] = m1;
        g_pl[pbase + wm + lq + 8] = l1;
    }
}

// ---------------------------------------------------------------------------
// Kernel 3: merge the 4 splits per q-tile.
// grid = (NQT, BB, 4), block 128: z covers rows z*16..z*16+15;
// thread: row = z*16 + tid>>3, 8 cols at (tid&7)*8.
// ---------------------------------------------------------------------------
__global__ __launch_bounds__(128) void merge_kernel(float* __restrict__ out)
{
    const int b   = blockIdx.y;
    const int idx = blockIdx.x;
    const int qi  = 63 - idx;
    const int tid = threadIdx.x;
    const int row = blockIdx.z * 16 + (tid >> 3);
    const int c8  = (tid & 7) * 8;

    const size_t pb = ((size_t)b * NPART + NSPLIT * idx) * 64;

    float mm[NSPLIT], ll[NSPLIT];
    float M = -1e30f;
    #pragma unroll
    for (int s = 0; s < NSPLIT; s++) {
        mm[s] = g_pm[pb + s * 64 + row];
        ll[s] = g_pl[pb + s * 64 + row];
        M = fmaxf(M, mm[s]);
    }
    float w[NSPLIT];
    float denom = 0.f;
    #pragma unroll
    for (int s = 0; s < NSPLIT; s++) {
        w[s] = (ll[s] > 0.f) ? __expf(mm[s] - M) : 0.f;
        denom += ll[s] * w[s];
    }
    float inv = 1.0f / denom;

    float acc[8];
    #pragma unroll
    for (int j = 0; j < 8; j++) acc[j] = 0.f;

    #pragma unroll
    for (int s = 0; s < NSPLIT; s++) {
        if (w[s] > 0.f) {
            const float* po = g_po + (pb + s * 64 + row) * HD + c8;
            #pragma unroll
            for (int j = 0; j < 8; j += 4) {
                float4 a = *(const float4*)&po[j];
                acc[j + 0] += a.x * w[s];
                acc[j + 1] += a.y * w[s];
                acc[j + 2] += a.z * w[s];
                acc[j + 3] += a.w * w[s];
            }
        }
    }

    float* op = out + ((size_t)b * SS + qi * 64 + row) * HD + c8;
    #pragma unroll
    for (int j = 0; j < 8; j += 4) {
        *(float4*)&op[j] = make_float4(acc[j] * inv, acc[j + 1] * inv,
                                       acc[j + 2] * inv, acc[j + 3] * inv);
    }
}

// ---------------------------------------------------------------------------
// kernel_launch
// ---------------------------------------------------------------------------
extern "C" void kernel_launch(void* const* d_in, const int* in_sizes, int n_in,
                              void* d_out, int out_size)
{
    const float* x  = (const float*)d_in[0];
    const float* Wq = (const float*)d_in[1];
    const float* Wk = (const float*)d_in[2];
    const float* Wv = (const float*)d_in[3];
    float* out = (float*)d_out;

    static int smem_set = 0;
    if (!smem_set) {
        cudaFuncSetAttribute(attn_kernel,
                             cudaFuncAttributeMaxDynamicSharedMemorySize,
                             SMEM_ATTN);
        smem_set = 1;
    }

    wpack_kernel<<<288, 256>>>(Wq, Wk, Wv);

    qkv_kernel<<<MM / 64, 256>>>(x);

    dim3 g2(NQT * NSPLIT, BB);
    attn_kernel<<<g2, 128, SMEM_ATTN>>>();

    dim3 g3(NQT, BB, 4);
    merge_kernel<<<g3, 128>>>(out);
}

// round 16
// speedup vs baseline: 1.6170x; 1.3820x over previous
#include <cuda_runtime.h>
#include <cuda_fp16.h>
#include <cstdint>

// Problem constants
#define BB   4
#define SS   4096
#define DIN  768
#define HD   64
#define MM   (BB*SS)   // 16384 rows
#define NSPLIT 4
#define NQT  64        // q-tiles per batch
#define NPART (NQT * NSPLIT)   // 256 partials per batch

// Scratch (device globals: allocation-free)
__device__ float g_po[BB * NPART * 64 * HD];   // unnormalized partial O
__device__ float g_pm[BB * NPART * 64];        // partial row max
__device__ float g_pl[BB * NPART * 64];        // partial row sum
// fp16 projections: Q pre-scaled by 1/8, row-major [s][d]; V transposed [d][s]
__device__ __align__(16) __half g_qh[MM * HD];
__device__ __align__(16) __half g_kh[MM * HD];
__device__ __align__(16) __half g_vt[BB * HD * SS];
// Packed W: [kfg=96][lr=4][n=192] of {tf32(W[k][n]), tf32(W[k+4][n])}
__device__ __align__(16) uint2 g_wp[96 * 4 * 192];

// ---------------------------------------------------------------------------
// helpers
// ---------------------------------------------------------------------------
__device__ __forceinline__ unsigned f2tf(float f) {
    unsigned u;
    asm("cvt.rna.tf32.f32 %0, %1;" : "=r"(u) : "f"(f));
    return u;
}
// tf32 m16n8k8 (qkv mainloop)
__device__ __forceinline__ void mma8(float* c, const unsigned* a,
                                     unsigned b0, unsigned b1) {
    asm("mma.sync.aligned.m16n8k8.row.col.f32.tf32.tf32.f32 "
        "{%0,%1,%2,%3},{%4,%5,%6,%7},{%8,%9},{%0,%1,%2,%3};"
        : "+f"(c[0]), "+f"(c[1]), "+f"(c[2]), "+f"(c[3])
        : "r"(a[0]), "r"(a[1]), "r"(a[2]), "r"(a[3]), "r"(b0), "r"(b1));
}
// fp16 m16n8k16 (attn)
__device__ __forceinline__ void mma16(float* c, const unsigned* a,
                                      unsigned b0, unsigned b1) {
    asm("mma.sync.aligned.m16n8k16.row.col.f32.f16.f16.f32 "
        "{%0,%1,%2,%3},{%4,%5,%6,%7},{%8,%9},{%0,%1,%2,%3};"
        : "+f"(c[0]), "+f"(c[1]), "+f"(c[2]), "+f"(c[3])
        : "r"(a[0]), "r"(a[1]), "r"(a[2]), "r"(a[3]), "r"(b0), "r"(b1));
}
__device__ __forceinline__ void cpa16(unsigned smem_dst, const void* gsrc) {
    asm volatile("cp.async.cg.shared.global [%0], [%1], 16;"
                 :: "r"(smem_dst), "l"(gsrc));
}
__device__ __forceinline__ void cpa_commit() {
    asm volatile("cp.async.commit_group;");
}
__device__ __forceinline__ void cpa_wait0() {
    asm volatile("cp.async.wait_group 0;");
}
__device__ __forceinline__ unsigned h2bits(__half2 h) {
    return *reinterpret_cast<unsigned*>(&h);
}

// ---------------------------------------------------------------------------
// Kernel 0: pack W into g_wp (tf32 rna, paired k/k+4).
// ---------------------------------------------------------------------------
__global__ __launch_bounds__(256) void wpack_kernel(
    const float* __restrict__ Wq,
    const float* __restrict__ Wk,
    const float* __restrict__ Wv)
{
    int idx = blockIdx.x * 256 + threadIdx.x;
    if (idx >= 96 * 4 * 192) return;
    int n  = idx % 192;
    int t  = idx / 192;
    int lr = t & 3;
    int kfg = t >> 2;
    int k = kfg * 8 + lr;
    int which = n >> 6, nc = n & 63;
    const float* W = (which == 0) ? Wq : (which == 1) ? Wk : Wv;
    g_wp[idx] = make_uint2(f2tf(W[(size_t)k * HD + nc]),
                           f2tf(W[(size_t)(k + 4) * HD + nc]));
}

// ---------------------------------------------------------------------------
// Kernel 1: fused QKV projection (tf32 mainloop, fp16 epilogue).
// BM=64, N=192 fused.  grid = 256, block 256.  8 warps = 4(m) x 2(n).
// ---------------------------------------------------------------------------
__global__ __launch_bounds__(256) void qkv_kernel(const float* __restrict__ x)
{
    __shared__ __align__(16) unsigned Xs2[2][64][40];
    __shared__ __align__(16) unsigned Ws2[2][16][392];

    const int tid  = threadIdx.x;
    const int lane = tid & 31;
    const int warp = tid >> 5;
    const int lq = lane >> 2;
    const int lr = lane & 3;
    const int wm = (warp >> 1) * 16;    // 0,16,32,48
    const int wn = (warp & 1) * 96;     // 0,96
    const int m0 = blockIdx.x * 64;

    float c[12][4];
    #pragma unroll
    for (int nf = 0; nf < 12; nf++)
        #pragma unroll
        for (int j = 0; j < 4; j++) c[nf][j] = 0.f;

    unsigned wdst[2][6];
    size_t   wsrc_off[6];
    #pragma unroll
    for (int r = 0; r < 6; r++) {
        int ch = tid + r * 256;
        int wrow = ch / 96;
        int wcol = ch - wrow * 96;
        wdst[0][r] = (unsigned)__cvta_generic_to_shared(
            (char*)&Ws2[0][0][0] + wrow * 1568 + wcol * 16);
        wdst[1][r] = (unsigned)__cvta_generic_to_shared(
            (char*)&Ws2[1][0][0] + wrow * 1568 + wcol * 16);
        wsrc_off[r] = (size_t)ch * 16;
    }

    const int xrow0 = tid >> 3, xc40 = (tid & 7) * 4;
    const int xrow1 = (tid + 256) >> 3, xc41 = ((tid + 256) & 7) * 4;

    float4 xreg[2];
    xreg[0] = *(const float4*)&x[(size_t)(m0 + xrow0) * DIN + xc40];
    xreg[1] = *(const float4*)&x[(size_t)(m0 + xrow1) * DIN + xc41];

    {
        const char* src = (const char*)g_wp;
        #pragma unroll
        for (int r = 0; r < 6; r++) cpa16(wdst[0][r], src + wsrc_off[r]);
        cpa_commit();
    }

    int p = 0;
    for (int k0 = 0; k0 < DIN; k0 += 32, p ^= 1) {
        {
            int kf = xc40 >> 3, pair = (xc40 >> 2) & 1;
            unsigned* d = &Xs2[p][xrow0][kf * 8 + pair];
            d[0] = f2tf(xreg[0].x); d[2] = f2tf(xreg[0].y);
            d[4] = f2tf(xreg[0].z); d[6] = f2tf(xreg[0].w);
        }
        {
            int kf = xc41 >> 3, pair = (xc41 >> 2) & 1;
            unsigned* d = &Xs2[p][xrow1][kf * 8 + pair];
            d[0] = f2tf(xreg[1].x); d[2] = f2tf(xreg[1].y);
            d[4] = f2tf(xreg[1].z); d[6] = f2tf(xreg[1].w);
        }

        cpa_wait0();
        __syncthreads();

        if (k0 + 32 < DIN) {
            xreg[0] = *(const float4*)&x[(size_t)(m0 + xrow0) * DIN + k0 + 32 + xc40];
            xreg[1] = *(const float4*)&x[(size_t)(m0 + xrow1) * DIN + k0 + 32 + xc41];
            const char* src = (const char*)g_wp + (size_t)((k0 >> 3) + 4) * 6144;
            #pragma unroll
            for (int r = 0; r < 6; r++) cpa16(wdst[p ^ 1][r], src + wsrc_off[r]);
            cpa_commit();
        }

        #pragma unroll
        for (int kf = 0; kf < 4; kf++) {
            uint2 xlo = *(const uint2*)&Xs2[p][wm + lq][(kf * 4 + lr) * 2];
            uint2 xhi = *(const uint2*)&Xs2[p][wm + lq + 8][(kf * 4 + lr) * 2];
            unsigned a[4] = {xlo.x, xhi.x, xlo.y, xhi.y};
            #pragma unroll
            for (int nf = 0; nf < 12; nf++) {
                uint2 b = *(const uint2*)&Ws2[p][kf * 4 + lr][(wn + nf * 8 + lq) * 2];
                mma8(c[nf], a, b.x, b.y);
            }
        }
    }

    // ---- epilogue: fp16 outputs; V transposed via smem (overlay on Xs2) ----
    __syncthreads();                        // all warps done with Xs2
    unsigned* VtsU = (unsigned*)&Xs2[0][0][0];   // [64 rows][37 words] (pitch 74 fp16)

    #pragma unroll
    for (int nf = 0; nf < 12; nf++) {
        int gcol = wn + nf * 8;
        int which = gcol >> 6;
        int nc = (gcol & 63) + 2 * lr;
        if (which == 0) {
            __half2 h0 = __floats2half2_rn(c[nf][0] * 0.125f, c[nf][1] * 0.125f);
            __half2 h1 = __floats2half2_rn(c[nf][2] * 0.125f, c[nf][3] * 0.125f);
            *(__half2*)&g_qh[(size_t)(m0 + wm + lq) * HD + nc] = h0;
            *(__half2*)&g_qh[(size_t)(m0 + wm + lq + 8) * HD + nc] = h1;
        } else if (which == 1) {
            __half2 h0 = __floats2half2_rn(c[nf][0], c[nf][1]);
            __half2 h1 = __floats2half2_rn(c[nf][2], c[nf][3]);
            *(__half2*)&g_kh[(size_t)(m0 + wm + lq) * HD + nc] = h0;
            *(__half2*)&g_kh[(size_t)(m0 + wm + lq + 8) * HD + nc] = h1;
        } else {
            __half2 h0 = __floats2half2_rn(c[nf][0], c[nf][1]);
            __half2 h1 = __floats2half2_rn(c[nf][2], c[nf][3]);
            int wrd = (gcol - 128) / 2 + lr;
            VtsU[(wm + lq) * 37 + wrd]     = h2bits(h0);
            VtsU[(wm + lq + 8) * 37 + wrd] = h2bits(h1);
        }
    }
    __syncthreads();

    {   // transposed V write: thread -> (dim n, 16-key segment)
        const __half* VtsH = (const __half*)VtsU;
        int n = tid >> 2, mseg = (tid & 3) * 16;
        int bat = m0 >> 12, s0g = m0 & (SS - 1);
        unsigned ow[8];
        #pragma unroll
        for (int i = 0; i < 8; i++) {
            __half2 hp = __halves2half2(VtsH[(mseg + 2 * i) * 74 + n],
                                        VtsH[(mseg + 2 * i + 1) * 74 + n]);
            ow[i] = h2bits(hp);
        }
        __half* dst = g_vt + ((size_t)(bat * HD + n)) * SS + s0g + mseg;
        *(uint4*)dst       = make_uint4(ow[0], ow[1], ow[2], ow[3]);
        *(uint4*)(dst + 8) = make_uint4(ow[4], ow[5], ow[6], ow[7]);
    }
}

// ---------------------------------------------------------------------------
// Kernel 2: causal flash attention, fp16 m16n8k16 + cp.async, SPLIT-K (4).
// grid = (256, B).  128 threads, 4 warps (each m16 x n64).  3 CTAs/SM.
// smem words: Ks[64][36] | Vt[2][64][36] | Qs[64][36] | Ps[64][36]
// ---------------------------------------------------------------------------
#define TW 36
#define TILE_W (64 * TW)
#define SMEM_ATTN (5 * TILE_W * (int)sizeof(unsigned))   // 46080 B

__global__ __launch_bounds__(128, 3) void attn_kernel()
{
    extern __shared__ unsigned smu[];
    unsigned* Ks = smu;                  // [64][36]
    unsigned* Vt = smu + TILE_W;         // [2][64][36]
    unsigned* Qs = smu + 3 * TILE_W;
    unsigned* Ps = smu + 4 * TILE_W;

    const int b     = blockIdx.y;
    const int qs    = blockIdx.x;
    const int idx   = qs >> 2;
    const int split = qs & 3;
    const int qi    = 63 - idx;
    const int nb    = qi + 1;
    const int qtr   = (nb + 3) >> 2;
    const int lo    = split * qtr;
    const int hi    = (lo + qtr < nb) ? (lo + qtr) : nb;

    const int tid  = threadIdx.x;
    const int lane = tid & 31;
    const int warp = tid >> 5;
    const int lq = lane >> 2;
    const int lr = lane & 3;
    const int wm = warp * 16;

    const size_t pbase = ((size_t)b * NPART + qs) * 64;

    if (lo >= hi) {
        if (tid < 64) {
            g_pm[pbase + tid] = -1e30f;
            g_pl[pbase + tid] = 0.f;
        }
        return;
    }

    const char* qh  = (const char*)(g_qh + ((size_t)b * SS + (size_t)qi * 64) * HD);
    const char* kh  = (const char*)(g_kh + (size_t)b * SS * HD);
    const char* vtp = (const char*)(g_vt + (size_t)b * HD * SS);

    unsigned ksb  = (unsigned)__cvta_generic_to_shared(Ks);
    unsigned vsb0 = (unsigned)__cvta_generic_to_shared(Vt);
    unsigned vsb1 = vsb0 + TILE_W * 4;
    unsigned qsb  = (unsigned)__cvta_generic_to_shared(Qs);

    const int ch = (tid & 7) * 16;       // 16B chunk offset within 128B row
    const int r0 = tid >> 3;             // base row (0..15), +16 per rep

    // K tile: row-major [key][d], 128B/row.  V tile: [dim][key], 128B/row.
    #define ISSUE_K(blk) do {                                                 \
        const char* _s = kh + (size_t)(blk) * 8192;                           \
        _Pragma("unroll")                                                     \
        for (int _i = 0; _i < 4; _i++) {                                      \
            int _row = r0 + 16 * _i;                                          \
            cpa16(ksb + _row * 144 + ch, _s + _row * 128 + ch);               \
        }                                                                     \
    } while (0)
    #define ISSUE_V(blk, vb) do {                                             \
        const char* _s = vtp + (size_t)(blk) * 128;                           \
        _Pragma("unroll")                                                     \
        for (int _i = 0; _i < 4; _i++) {                                      \
            int _row = r0 + 16 * _i;                                          \
            cpa16((vb) + _row * 144 + ch, _s + (size_t)_row * (SS * 2) + ch); \
        }                                                                     \
    } while (0)

    // ---- initial: Q + K[lo] + V[lo] ----
    #pragma unroll
    for (int i = 0; i < 4; i++) {
        int row = r0 + 16 * i;
        cpa16(qsb + row * 144 + ch, qh + row * 128 + ch);
    }
    ISSUE_K(lo);
    ISSUE_V(lo, vsb0);
    cpa_commit();

    float m0s = -1e30f, m1s = -1e30f, l0 = 0.f, l1 = 0.f;
    float o[8][4];
    #pragma unroll
    for (int nf = 0; nf < 8; nf++)
        #pragma unroll
        for (int j = 0; j < 4; j++) o[nf][j] = 0.f;

    cpa_wait0();
    __syncthreads();

    // ---- Q fragments (A, m16n8k16): 4 k-chunks x 4 regs ----
    unsigned aq[4][4];
    #pragma unroll
    for (int kf = 0; kf < 4; kf++) {
        aq[kf][0] = Qs[(wm + lq) * TW + kf * 8 + lr];
        aq[kf][1] = Qs[(wm + lq + 8) * TW + kf * 8 + lr];
        aq[kf][2] = Qs[(wm + lq) * TW + kf * 8 + 4 + lr];
        aq[kf][3] = Qs[(wm + lq + 8) * TW + kf * 8 + 4 + lr];
    }

    for (int kb = lo; kb < hi; kb++) {
        const int par = (kb - lo) & 1;
        unsigned* Vb = Vt + par * TILE_W;

        if (kb + 1 < hi) {
            ISSUE_V(kb + 1, par ? vsb0 : vsb1);
            cpa_commit();
        }

        // ---- S = Q K^T ----
        float s[8][4];
        #pragma unroll
        for (int nf = 0; nf < 8; nf++)
            #pragma unroll
            for (int j = 0; j < 4; j++) s[nf][j] = 0.f;

        #pragma unroll
        for (int kf = 0; kf < 4; kf++) {
            #pragma unroll
            for (int nf = 0; nf < 8; nf++) {
                unsigned b0 = Ks[(nf * 8 + lq) * TW + kf * 8 + lr];
                unsigned b1 = Ks[(nf * 8 + lq) * TW + kf * 8 + 4 + lr];
                mma16(s[nf], aq[kf], b0, b1);
            }
        }
        __syncthreads();

        if (kb + 1 < hi) {
            ISSUE_K(kb + 1);
            cpa_commit();
        }

        // causal mask on diagonal block
        if (kb == qi) {
            int rr0 = wm + lq, rr1 = rr0 + 8;
            #pragma unroll
            for (int nf = 0; nf < 8; nf++) {
                int cc = nf * 8 + 2 * lr;
                if (cc     > rr0) s[nf][0] = -1e30f;
                if (cc + 1 > rr0) s[nf][1] = -1e30f;
                if (cc     > rr1) s[nf][2] = -1e30f;
                if (cc + 1 > rr1) s[nf][3] = -1e30f;
            }
        }

        // ---- online softmax ----
        float mx0 = -1e30f, mx1 = -1e30f;
        #pragma unroll
        for (int nf = 0; nf < 8; nf++) {
            mx0 = fmaxf(mx0, fmaxf(s[nf][0], s[nf][1]));
            mx1 = fmaxf(mx1, fmaxf(s[nf][2], s[nf][3]));
        }
        mx0 = fmaxf(mx0, __shfl_xor_sync(0xffffffffu, mx0, 1));
        mx0 = fmaxf(mx0, __shfl_xor_sync(0xffffffffu, mx0, 2));
        mx1 = fmaxf(mx1, __shfl_xor_sync(0xffffffffu, mx1, 1));
        mx1 = fmaxf(mx1, __shfl_xor_sync(0xffffffffu, mx1, 2));

        float mn0 = fmaxf(m0s, mx0), mn1 = fmaxf(m1s, mx1);
        float corr0 = __expf(m0s - mn0), corr1 = __expf(m1s - mn1);

        float sum0 = 0.f, sum1 = 0.f;
        #pragma unroll
        for (int nf = 0; nf < 8; nf++) {
            s[nf][0] = __expf(s[nf][0] - mn0);
            s[nf][1] = __expf(s[nf][1] - mn0);
            s[nf][2] = __expf(s[nf][2] - mn1);
            s[nf][3] = __expf(s[nf][3] - mn1);
            sum0 += s[nf][0] + s[nf][1];
            sum1 += s[nf][2] + s[nf][3];
        }
        sum0 += __shfl_xor_sync(0xffffffffu, sum0, 1);
        sum0 += __shfl_xor_sync(0xffffffffu, sum0, 2);
        sum1 += __shfl_xor_sync(0xffffffffu, sum1, 1);
        sum1 += __shfl_xor_sync(0xffffffffu, sum1, 2);

        l0 = l0 * corr0 + sum0;  m0s = mn0;
        l1 = l1 * corr1 + sum1;  m1s = mn1;

        #pragma unroll
        for (int nf = 0; nf < 8; nf++) {
            o[nf][0] *= corr0; o[nf][1] *= corr0;
            o[nf][2] *= corr1; o[nf][3] *= corr1;
        }

        // ---- P -> smem as fp16 pairs (warp-private rows) ----
        #pragma unroll
        for (int nf = 0; nf < 8; nf++) {
            __half2 h0 = __floats2half2_rn(s[nf][0], s[nf][1]);
            __half2 h1 = __floats2half2_rn(s[nf][2], s[nf][3]);
            Ps[(wm + lq) * TW + nf * 4 + lr]     = h2bits(h0);
            Ps[(wm + lq + 8) * TW + nf * 4 + lr] = h2bits(h1);
        }
        __syncwarp();

        // ---- O += P V ----
        #pragma unroll
        for (int kf = 0; kf < 4; kf++) {
            unsigned ap[4];
            ap[0] = Ps[(wm + lq) * TW + kf * 8 + lr];
            ap[1] = Ps[(wm + lq + 8) * TW + kf * 8 + lr];
            ap[2] = Ps[(wm + lq) * TW + kf * 8 + 4 + lr];
            ap[3] = Ps[(wm + lq + 8) * TW + kf * 8 + 4 + lr];
            #pragma unroll
            for (int nf = 0; nf < 8; nf++) {
                unsigned b0 = Vb[(nf * 8 + lq) * TW + kf * 8 + lr];
                unsigned b1 = Vb[(nf * 8 + lq) * TW + kf * 8 + 4 + lr];
                mma16(o[nf], ap, b0, b1);
            }
        }

        cpa_wait0();
        __syncthreads();
    }

    // ---- write partials ----
    #pragma unroll
    for (int nf = 0; nf < 8; nf++) {
        int cc = nf * 8 + 2 * lr;
        *(float2*)&g_po[(pbase + wm + lq) * HD + cc] =
            make_float2(o[nf][0], o[nf][1]);
        *(float2*)&g_po[(pbase + wm + lq + 8) * HD + cc] =
            make_float2(o[nf][2], o[nf][3]);
    }
    if (lr == 0) {
        g_pm[pbase + wm + lq]     = m0s;
        g_pl[pbase + wm + lq]     = l0;
        g_pm[pbase + wm + lq + 8] = m1s;
        g_pl[pbase + wm + lq + 8] = l1;
    }
}

// ---------------------------------------------------------------------------
// Kernel 3: merge the 4 splits per q-tile.  grid = (NQT, BB, 4), block 128.
// ---------------------------------------------------------------------------
__global__ __launch_bounds__(128) void merge_kernel(float* __restrict__ out)
{
    const int b   = blockIdx.y;
    const int idx = blockIdx.x;
    const int qi  = 63 - idx;
    const int tid = threadIdx.x;
    const int row = blockIdx.z * 16 + (tid >> 3);
    const int c8  = (tid & 7) * 8;

    const size_t pb = ((size_t)b * NPART + NSPLIT * idx) * 64;

    float mm[NSPLIT], ll[NSPLIT];
    float M = -1e30f;
    #pragma unroll
    for (int s = 0; s < NSPLIT; s++) {
        mm[s] = g_pm[pb + s * 64 + row];
        ll[s] = g_pl[pb + s * 64 + row];
        M = fmaxf(M, mm[s]);
    }
    float w[NSPLIT];
    float denom = 0.f;
    #pragma unroll
    for (int s = 0; s < NSPLIT; s++) {
        w[s] = (ll[s] > 0.f) ? __expf(mm[s] - M) : 0.f;
        denom += ll[s] * w[s];
    }
    float inv = 1.0f / denom;

    float acc[8];
    #pragma unroll
    for (int j = 0; j < 8; j++) acc[j] = 0.f;

    #pragma unroll
    for (int s = 0; s < NSPLIT; s++) {
        if (w[s] > 0.f) {
            const float* po = g_po + (pb + s * 64 + row) * HD + c8;
            #pragma unroll
            for (int j = 0; j < 8; j += 4) {
                float4 a = *(const float4*)&po[j];
                acc[j + 0] += a.x * w[s];
                acc[j + 1] += a.y * w[s];
                acc[j + 2] += a.z * w[s];
                acc[j + 3] += a.w * w[s];
            }
        }
    }

    float* op = out + ((size_t)b * SS + qi * 64 + row) * HD + c8;
    #pragma unroll
    for (int j = 0; j < 8; j += 4) {
        *(float4*)&op[j] = make_float4(acc[j] * inv, acc[j + 1] * inv,
                                       acc[j + 2] * inv, acc[j + 3] * inv);
    }
}

// ---------------------------------------------------------------------------
// kernel_launch
// ---------------------------------------------------------------------------
extern "C" void kernel_launch(void* const* d_in, const int* in_sizes, int n_in,
                              void* d_out, int out_size)
{
    const float* x  = (const float*)d_in[0];
    const float* Wq = (const float*)d_in[1];
    const float* Wk = (const float*)d_in[2];
    const float* Wv = (const float*)d_in[3];
    float* out = (float*)d_out;

    static int smem_set = 0;
    if (!smem_set) {
        cudaFuncSetAttribute(attn_kernel,
                             cudaFuncAttributeMaxDynamicSharedMemorySize,
                             SMEM_ATTN);
        smem_set = 1;
    }

    wpack_kernel<<<288, 256>>>(Wq, Wk, Wv);

    qkv_kernel<<<MM / 64, 256>>>(x);

    dim3 g2(NQT * NSPLIT, BB);
    attn_kernel<<<g2, 128, SMEM_ATTN>>>();

    dim3 g3(NQT, BB, 4);
    merge_kernel<<<g3, 128>>>(out);
}